// round 3
// baseline (speedup 1.0000x reference)
#include <cuda_runtime.h>
#include <cuda_fp16.h>
#include <math.h>

#define B_ 64
#define H_ 4
#define N_ 16384
#define W_ 64
#define D_ 1024
#define P_ 70
#define R_ 280
#define BT 8
#define RT 10

// Scratch (device globals: allocation-free rule)
__device__ float  g_params[B_ * R_];     // raw GEMM output
__device__ __half g_ebuf[B_ * H_ * N_];  // exp(beta*cos_sim), fp16, 8 MB
__device__ float  g_kv[B_ * H_ * W_];    // key * beta / ||key||
__device__ float  g_hp[B_ * H_ * 8];     // gate, sh0, sh1, sh2, gamma
__device__ float  g_sum[B_ * H_];        // softmax denominators (atomic)
__device__ float  g_psum[B_ * H_];       // pow-sharpen denominators (atomic)

__device__ __forceinline__ float softplusf(float x) {
    return x > 20.f ? x : log1pf(__expf(x));
}

// sm_103a packed f32x2 FMA
__device__ __forceinline__ unsigned long long ff2(unsigned long long a,
                                                  unsigned long long b,
                                                  unsigned long long c) {
    unsigned long long d;
    asm("fma.rn.f32x2 %0, %1, %2, %3;" : "=l"(d) : "l"(a), "l"(b), "l"(c));
    return d;
}
__device__ __forceinline__ void f4pack(float4 v, unsigned long long& lo,
                                       unsigned long long& hi) {
    asm("mov.b64 %0, {%2, %3};\n\tmov.b64 %1, {%4, %5};"
        : "=l"(lo), "=l"(hi) : "f"(v.x), "f"(v.y), "f"(v.z), "f"(v.w));
}
__device__ __forceinline__ float hsum2(unsigned long long v) {
    float x, y;
    asm("mov.b64 {%0, %1}, %2;" : "=f"(x), "=f"(y) : "l"(v));
    return x + y;
}

// ---------------------------------------------------------------------------
// Kernel A: tiled GEMM (unchanged from R2 — ~3us)
// ---------------------------------------------------------------------------
__global__ __launch_bounds__(256) void kparams(const float* __restrict__ cs,
                                               const float* __restrict__ Wr,
                                               const float* __restrict__ br) {
    extern __shared__ float4 dynp[];
    float4* scs = dynp;
    float4* sw  = dynp + BT * 256;
    int rt = blockIdx.x, bt = blockIdx.y;
    int tid = threadIdx.x;

    const float4* gcs = (const float4*)cs + (size_t)bt * BT * 256;
    #pragma unroll
    for (int i = 0; i < BT; i++) scs[i * 256 + tid] = gcs[i * 256 + tid];
    const float4* gw = (const float4*)Wr + (size_t)rt * RT * 256;
    #pragma unroll
    for (int i = 0; i < RT; i++) sw[i * 256 + tid] = gw[i * 256 + tid];
    __syncthreads();

    int w = tid >> 5, l = tid & 31;
    const float4* a = scs + w * 256;
    #pragma unroll
    for (int rl = 0; rl < RT; rl++) {
        const float4* bv = sw + rl * 256;
        float4 acc = make_float4(0.f, 0.f, 0.f, 0.f);
        #pragma unroll
        for (int j = 0; j < 8; j++) {
            float4 x = a[j * 32 + l], y = bv[j * 32 + l];
            acc.x = fmaf(x.x, y.x, acc.x);
            acc.y = fmaf(x.y, y.y, acc.y);
            acc.z = fmaf(x.z, y.z, acc.z);
            acc.w = fmaf(x.w, y.w, acc.w);
        }
        float s = (acc.x + acc.y) + (acc.z + acc.w);
        #pragma unroll
        for (int o = 16; o; o >>= 1) s += __shfl_xor_sync(0xffffffffu, s, o);
        if (l == 0) {
            int r = rt * RT + rl;
            g_params[(bt * BT + w) * R_ + r] = s + br[r];
        }
    }
}

// ---------------------------------------------------------------------------
// Kernel A2: one warp per (b,h): key norm + activations.
// ---------------------------------------------------------------------------
__global__ __launch_bounds__(256) void kderive() {
    int gw = (blockIdx.x * 256 + threadIdx.x) >> 5;
    int l = threadIdx.x & 31;
    int b = gw >> 2, h = gw & 3;
    const float* ps = &g_params[b * R_ + h * P_];
    float v0 = ps[l], v1 = ps[l + 32];
    float v2 = (l < 6) ? ps[l + 64] : 0.f;

    float kn2 = fmaf(v0, v0, v1 * v1);
    #pragma unroll
    for (int o = 16; o; o >>= 1) kn2 += __shfl_xor_sync(0xffffffffu, kn2, o);

    float p64 = __shfl_sync(0xffffffffu, v2, 0);
    float p65 = __shfl_sync(0xffffffffu, v2, 1);
    float p66 = __shfl_sync(0xffffffffu, v2, 2);
    float p67 = __shfl_sync(0xffffffffu, v2, 3);
    float p68 = __shfl_sync(0xffffffffu, v2, 4);
    float p69 = __shfl_sync(0xffffffffu, v2, 5);

    float beta = softplusf(p64);
    float scale = beta / fmaxf(sqrtf(kn2), 1e-8f);
    g_kv[gw * W_ + l]      = v0 * scale;
    g_kv[gw * W_ + 32 + l] = v1 * scale;

    if (l == 0) {
        float gate = 1.f / (1.f + __expf(-p65));
        float m = fmaxf(p66, fmaxf(p67, p68));
        float e0 = __expf(p66 - m), e1 = __expf(p67 - m), e2 = __expf(p68 - m);
        float si = 1.f / (e0 + e1 + e2);
        g_hp[gw * 8 + 0] = gate;
        g_hp[gw * 8 + 1] = e0 * si;
        g_hp[gw * 8 + 2] = e1 * si;
        g_hp[gw * 8 + 3] = e2 * si;
        g_hp[gw * 8 + 4] = 1.f + softplusf(p69);
        g_sum[gw] = 0.f;
        g_psum[gw] = 0.f;
    }
}

// ---------------------------------------------------------------------------
// Kernel B: stream memory once, register-resident. 4 threads (quad) per row,
// each owns a 64B segment loaded directly from global (no smem staging).
// Quad shfl-reduce -> leader computes exp -> smem restage -> coalesced fp16
// writes + softmax-sum atomics.
// ---------------------------------------------------------------------------
__global__ __launch_bounds__(512) void kdots(const float* __restrict__ mem) {
    __shared__ float4 skv4[H_ * 16];     // 4 heads x 16 float4
    __shared__ __half se[H_ * 128];      // [h][row] staging
    __shared__ float sred[16];
    int b = blockIdx.y;
    int n0 = blockIdx.x * 128;
    int tid = threadIdx.x;
    int row = tid >> 2, seg = tid & 3;

    if (tid < H_ * 16) skv4[tid] = ((const float4*)(g_kv + b * H_ * W_))[tid];
    __syncthreads();

    const float4* src = (const float4*)(mem + ((size_t)b * N_ + n0) * W_);
    int fi = row * 16 + seg * 4;
    float4 m0 = src[fi + 0];
    float4 m1 = src[fi + 1];
    float4 m2 = src[fi + 2];
    float4 m3 = src[fi + 3];

    unsigned long long ml[8];
    f4pack(m0, ml[0], ml[1]); f4pack(m1, ml[2], ml[3]);
    f4pack(m2, ml[4], ml[5]); f4pack(m3, ml[6], ml[7]);

    unsigned long long ssq = 0, d0 = 0, d1 = 0, d2 = 0, d3 = 0;
    #pragma unroll
    for (int q = 0; q < 8; q++) ssq = ff2(ml[q], ml[q], ssq);
    #pragma unroll
    for (int j = 0; j < 4; j++) {
        unsigned long long klo, khi;
        f4pack(skv4[      seg * 4 + j], klo, khi);
        d0 = ff2(klo, ml[2*j], d0); d0 = ff2(khi, ml[2*j+1], d0);
        f4pack(skv4[16 + seg * 4 + j], klo, khi);
        d1 = ff2(klo, ml[2*j], d1); d1 = ff2(khi, ml[2*j+1], d1);
        f4pack(skv4[32 + seg * 4 + j], klo, khi);
        d2 = ff2(klo, ml[2*j], d2); d2 = ff2(khi, ml[2*j+1], d2);
        f4pack(skv4[48 + seg * 4 + j], klo, khi);
        d3 = ff2(klo, ml[2*j], d3); d3 = ff2(khi, ml[2*j+1], d3);
    }

    float sq = hsum2(ssq);
    float f0 = hsum2(d0), f1 = hsum2(d1), f2 = hsum2(d2), f3 = hsum2(d3);
    #pragma unroll
    for (int o = 1; o < 4; o <<= 1) {
        sq += __shfl_xor_sync(0xffffffffu, sq, o);
        f0 += __shfl_xor_sync(0xffffffffu, f0, o);
        f1 += __shfl_xor_sync(0xffffffffu, f1, o);
        f2 += __shfl_xor_sync(0xffffffffu, f2, o);
        f3 += __shfl_xor_sync(0xffffffffu, f3, o);
    }
    if (seg == 0) {
        float inv = 1.f / fmaxf(sqrtf(sq), 1e-8f);
        se[row]       = __float2half(__expf(f0 * inv));
        se[128 + row] = __float2half(__expf(f1 * inv));
        se[256 + row] = __float2half(__expf(f2 * inv));
        se[384 + row] = __float2half(__expf(f3 * inv));
    }
    __syncthreads();

    // tid -> plane p = tid>>7, r = tid&127 : coalesced fp16 store + block sum
    int p = tid >> 7, r = tid & 127;
    __half hv = se[p * 128 + r];
    g_ebuf[((size_t)(b * H_ + p)) * N_ + n0 + r] = hv;
    float v = __half2float(hv);
    #pragma unroll
    for (int o = 16; o; o >>= 1) v += __shfl_xor_sync(0xffffffffu, v, o);
    if ((tid & 31) == 0) sred[tid >> 5] = v;     // warps 4p..4p+3 hold plane p
    __syncthreads();
    if (tid < 4) {
        float t = sred[tid*4] + sred[tid*4+1] + sred[tid*4+2] + sred[tid*4+3];
        atomicAdd(&g_sum[b * H_ + tid], t);
    }
}

// ---------------------------------------------------------------------------
// Kernel C1: gated -> shift -> pow, written UNNORMALIZED into d_out, plus one
// block atomic of the pow-sum. Full grid parallelism, pow computed once.
// ---------------------------------------------------------------------------
__global__ __launch_bounds__(256) void kf1(const float* __restrict__ prev,
                                           float* __restrict__ out) {
    __shared__ float sred[8];
    int bh = blockIdx.y;
    int i0 = blockIdx.x * 256 + threadIdx.x;    // float4 index in row (0..4095)
    int lane = threadIdx.x & 31;

    const float* hp = &g_hp[bh * 8];
    float gate = hp[0], sh0 = hp[1], sh1 = hp[2], sh2 = hp[3], gamma = hp[4];
    float a = gate / g_sum[bh];
    float om = 1.f - gate;

    size_t base = (size_t)bh * N_;
    const __half* e = g_ebuf + base;
    const __half2* e2 = (const __half2*)e;
    float4 p = ((const float4*)(prev + base))[i0];
    float2 fa = __half22float2(e2[2 * i0]);
    float2 fb = __half22float2(e2[2 * i0 + 1]);

    float4 g;
    g.x = fmaf(a, fa.x, om * p.x);
    g.y = fmaf(a, fa.y, om * p.y);
    g.z = fmaf(a, fb.x, om * p.z);
    g.w = fmaf(a, fb.y, om * p.w);

    int n = i0 * 4;
    float left = __shfl_up_sync(0xffffffffu, g.w, 1);
    if (lane == 0) {
        int nl = (n + N_ - 1) & (N_ - 1);
        left = fmaf(a, __half2float(e[nl]), om * prev[base + nl]);
    }
    float right = __shfl_down_sync(0xffffffffu, g.x, 1);
    if (lane == 31) {
        int nr = (n + 4) & (N_ - 1);
        right = fmaf(a, __half2float(e[nr]), om * prev[base + nr]);
    }

    float v0 = fmaf(sh0, left, fmaf(sh1, g.x, sh2 * g.y));
    float v1 = fmaf(sh0, g.x, fmaf(sh1, g.y, sh2 * g.z));
    float v2 = fmaf(sh0, g.y, fmaf(sh1, g.z, sh2 * g.w));
    float v3 = fmaf(sh0, g.z, fmaf(sh1, g.w, sh2 * right));

    float w0 = __powf(v0, gamma), w1 = __powf(v1, gamma);
    float w2 = __powf(v2, gamma), w3 = __powf(v3, gamma);
    ((float4*)(out + base))[i0] = make_float4(w0, w1, w2, w3);

    float ls = (w0 + w1) + (w2 + w3);
    #pragma unroll
    for (int o = 16; o; o >>= 1) ls += __shfl_xor_sync(0xffffffffu, ls, o);
    if (lane == 0) sred[threadIdx.x >> 5] = ls;
    __syncthreads();
    if (threadIdx.x == 0) {
        float t = 0.f;
        #pragma unroll
        for (int w = 0; w < 8; w++) t += sred[w];
        atomicAdd(&g_psum[bh], t);
    }
}

// ---------------------------------------------------------------------------
// Kernel C2: in-place scale of d_out (reads hit L2 dirty lines from kf1).
// ---------------------------------------------------------------------------
__global__ __launch_bounds__(256) void kf2(float* __restrict__ out) {
    int gid = blockIdx.x * 256 + threadIdx.x;
    int i0 = gid * 2;                  // float4 index; 4096 per row => bh = i0>>12
    float invT = 1.f / (g_psum[i0 >> 12] + 1e-6f);
    float4* o4 = (float4*)out;
    float4 x = o4[i0], y = o4[i0 + 1];
    x.x *= invT; x.y *= invT; x.z *= invT; x.w *= invT;
    y.x *= invT; y.y *= invT; y.z *= invT; y.w *= invT;
    o4[i0] = x; o4[i0 + 1] = y;
}

// ---------------------------------------------------------------------------
extern "C" void kernel_launch(void* const* d_in, const int* in_sizes, int n_in,
                              void* d_out, int out_size) {
    const float* cs   = (const float*)d_in[0];
    const float* prev = (const float*)d_in[1];
    const float* mem  = (const float*)d_in[2];
    const float* Wr   = (const float*)d_in[3];
    const float* br   = (const float*)d_in[4];
    float* out = (float*)d_out;

    static int inited = 0;
    if (!inited) {
        cudaFuncSetAttribute(kparams, cudaFuncAttributeMaxDynamicSharedMemorySize,
                             (BT + RT) * 256 * 16);
        inited = 1;
    }

    kparams<<<dim3(R_ / RT, B_ / BT), 256, (BT + RT) * 256 * 16>>>(cs, Wr, br);
    kderive<<<(B_ * H_) / 8, 256>>>();
    kdots<<<dim3(N_ / 128, B_), 512>>>(mem);
    kf1<<<dim3(N_ / 1024, B_ * H_), 256>>>(prev, out);
    kf2<<<(B_ * H_ * N_ / 4) / 512, 256>>>(out);
}

// round 4
// speedup vs baseline: 1.4229x; 1.4229x over previous
#include <cuda_runtime.h>
#include <cuda_fp16.h>
#include <math.h>

#define B_ 64
#define H_ 4
#define N_ 16384
#define W_ 64
#define D_ 1024
#define P_ 70
#define R_ 280
#define BT 8
#define RT 10

// Scratch (device globals: allocation-free rule)
__device__ float  g_params[B_ * R_];     // raw GEMM output
__device__ __half g_ebuf[B_ * H_ * N_];  // exp(beta*cos_sim), fp16, 8 MB
__device__ float  g_kv[B_ * H_ * W_];    // key * beta / ||key||
__device__ float  g_hp[B_ * H_ * 8];     // gate, sh0, sh1, sh2, gamma
__device__ float  g_sum[B_ * H_];        // softmax denominators (atomic)
__device__ float  g_psum[B_ * H_];       // pow-sharpen denominators (atomic)

__device__ __forceinline__ float softplusf(float x) {
    return x > 20.f ? x : log1pf(__expf(x));
}

// ---------------------------------------------------------------------------
// Kernel A: tiled GEMM
// ---------------------------------------------------------------------------
__global__ __launch_bounds__(256) void kparams(const float* __restrict__ cs,
                                               const float* __restrict__ Wr,
                                               const float* __restrict__ br) {
    extern __shared__ float4 dynp[];
    float4* scs = dynp;
    float4* sw  = dynp + BT * 256;
    int rt = blockIdx.x, bt = blockIdx.y;
    int tid = threadIdx.x;

    const float4* gcs = (const float4*)cs + (size_t)bt * BT * 256;
    #pragma unroll
    for (int i = 0; i < BT; i++) scs[i * 256 + tid] = gcs[i * 256 + tid];
    const float4* gw = (const float4*)Wr + (size_t)rt * RT * 256;
    #pragma unroll
    for (int i = 0; i < RT; i++) sw[i * 256 + tid] = gw[i * 256 + tid];
    __syncthreads();

    int w = tid >> 5, l = tid & 31;
    const float4* a = scs + w * 256;
    #pragma unroll
    for (int rl = 0; rl < RT; rl++) {
        const float4* bv = sw + rl * 256;
        float4 acc = make_float4(0.f, 0.f, 0.f, 0.f);
        #pragma unroll
        for (int j = 0; j < 8; j++) {
            float4 x = a[j * 32 + l], y = bv[j * 32 + l];
            acc.x = fmaf(x.x, y.x, acc.x);
            acc.y = fmaf(x.y, y.y, acc.y);
            acc.z = fmaf(x.z, y.z, acc.z);
            acc.w = fmaf(x.w, y.w, acc.w);
        }
        float s = (acc.x + acc.y) + (acc.z + acc.w);
        #pragma unroll
        for (int o = 16; o; o >>= 1) s += __shfl_xor_sync(0xffffffffu, s, o);
        if (l == 0) {
            int r = rt * RT + rl;
            g_params[(bt * BT + w) * R_ + r] = s + br[r];
        }
    }
}

// ---------------------------------------------------------------------------
// Kernel A2: one warp per (b,h): key norm + activations.
// ---------------------------------------------------------------------------
__global__ __launch_bounds__(256) void kderive() {
    int gw = (blockIdx.x * 256 + threadIdx.x) >> 5;
    int l = threadIdx.x & 31;
    int b = gw >> 2, h = gw & 3;
    const float* ps = &g_params[b * R_ + h * P_];
    float v0 = ps[l], v1 = ps[l + 32];
    float v2 = (l < 6) ? ps[l + 64] : 0.f;

    float kn2 = fmaf(v0, v0, v1 * v1);
    #pragma unroll
    for (int o = 16; o; o >>= 1) kn2 += __shfl_xor_sync(0xffffffffu, kn2, o);

    float p64 = __shfl_sync(0xffffffffu, v2, 0);
    float p65 = __shfl_sync(0xffffffffu, v2, 1);
    float p66 = __shfl_sync(0xffffffffu, v2, 2);
    float p67 = __shfl_sync(0xffffffffu, v2, 3);
    float p68 = __shfl_sync(0xffffffffu, v2, 4);
    float p69 = __shfl_sync(0xffffffffu, v2, 5);

    float beta = softplusf(p64);
    float scale = beta / fmaxf(sqrtf(kn2), 1e-8f);
    g_kv[gw * W_ + l]      = v0 * scale;
    g_kv[gw * W_ + 32 + l] = v1 * scale;

    if (l == 0) {
        float gate = 1.f / (1.f + __expf(-p65));
        float m = fmaxf(p66, fmaxf(p67, p68));
        float e0 = __expf(p66 - m), e1 = __expf(p67 - m), e2 = __expf(p68 - m);
        float si = 1.f / (e0 + e1 + e2);
        g_hp[gw * 8 + 0] = gate;
        g_hp[gw * 8 + 1] = e0 * si;
        g_hp[gw * 8 + 2] = e1 * si;
        g_hp[gw * 8 + 3] = e2 * si;
        g_hp[gw * 8 + 4] = 1.f + softplusf(p69);
        g_sum[gw] = 0.f;
        g_psum[gw] = 0.f;
    }
}

// ---------------------------------------------------------------------------
// Kernel B: stream memory once. 256 rows/block via smem tile (stride-17
// float4 = conflict-free LDS.128). Plain scalar FMA (no packing movs) —
// issue cost hides under the DRAM stream. fp16 ebuf via staged half2 writes.
// ---------------------------------------------------------------------------
__global__ __launch_bounds__(256) void kdots(const float* __restrict__ mem) {
    extern __shared__ float4 dynd[];     // 256 rows * 17 float4
    __shared__ float4 skv4[H_ * 16];
    __shared__ float sred[32];
    __shared__ __half se[H_ * 256];
    int b = blockIdx.y;
    int n0 = blockIdx.x * 256;
    int tid = threadIdx.x;

    if (tid < H_ * 16) skv4[tid] = ((const float4*)(g_kv + b * H_ * W_))[tid];

    const float4* src = (const float4*)(mem + ((size_t)b * N_ + n0) * W_);
    #pragma unroll
    for (int j = 0; j < 16; j++) {
        int f = j * 256 + tid;
        dynd[(f >> 4) * 17 + (f & 15)] = src[f];
    }
    __syncthreads();

    float ssq = 0.f, d0 = 0.f, d1 = 0.f, d2 = 0.f, d3 = 0.f;
    const float4* mr = dynd + tid * 17;
    #pragma unroll
    for (int j = 0; j < 16; j++) {
        float4 m = mr[j];
        float4 a0 = skv4[j], a1 = skv4[16 + j], a2 = skv4[32 + j], a3 = skv4[48 + j];
        ssq = fmaf(m.x, m.x, ssq); ssq = fmaf(m.y, m.y, ssq);
        ssq = fmaf(m.z, m.z, ssq); ssq = fmaf(m.w, m.w, ssq);
        d0 = fmaf(a0.x, m.x, d0); d0 = fmaf(a0.y, m.y, d0);
        d0 = fmaf(a0.z, m.z, d0); d0 = fmaf(a0.w, m.w, d0);
        d1 = fmaf(a1.x, m.x, d1); d1 = fmaf(a1.y, m.y, d1);
        d1 = fmaf(a1.z, m.z, d1); d1 = fmaf(a1.w, m.w, d1);
        d2 = fmaf(a2.x, m.x, d2); d2 = fmaf(a2.y, m.y, d2);
        d2 = fmaf(a2.z, m.z, d2); d2 = fmaf(a2.w, m.w, d2);
        d3 = fmaf(a3.x, m.x, d3); d3 = fmaf(a3.y, m.y, d3);
        d3 = fmaf(a3.z, m.z, d3); d3 = fmaf(a3.w, m.w, d3);
    }

    float inv = 1.f / fmaxf(sqrtf(ssq), 1e-8f);
    __half h0 = __float2half(__expf(d0 * inv));
    __half h1 = __float2half(__expf(d1 * inv));
    __half h2 = __float2half(__expf(d2 * inv));
    __half h3 = __float2half(__expf(d3 * inv));
    se[tid]       = h0;
    se[256 + tid] = h1;
    se[512 + tid] = h2;
    se[768 + tid] = h3;

    // softmax-denominator partials (sum of the SAME rounded fp16 values)
    float s0 = __half2float(h0), s1 = __half2float(h1);
    float s2 = __half2float(h2), s3 = __half2float(h3);
    #pragma unroll
    for (int o = 16; o; o >>= 1) {
        s0 += __shfl_xor_sync(0xffffffffu, s0, o);
        s1 += __shfl_xor_sync(0xffffffffu, s1, o);
        s2 += __shfl_xor_sync(0xffffffffu, s2, o);
        s3 += __shfl_xor_sync(0xffffffffu, s3, o);
    }
    if ((tid & 31) == 0) {
        int wp = tid >> 5;
        sred[wp * 4 + 0] = s0; sred[wp * 4 + 1] = s1;
        sred[wp * 4 + 2] = s2; sred[wp * 4 + 3] = s3;
    }
    __syncthreads();

    // coalesced half2 stores: plane p = tid>>6, two chunks of 64 half2
    {
        int p = tid >> 6, c = tid & 63;
        __half2* dst = (__half2*)(g_ebuf + ((size_t)(b * H_ + p)) * N_ + n0);
        const __half2* s2p = (const __half2*)(se + p * 256);
        dst[c] = s2p[c];
        dst[c + 64] = s2p[c + 64];
    }
    if (tid < 4) {
        float t = 0.f;
        #pragma unroll
        for (int wp = 0; wp < 8; wp++) t += sred[wp * 4 + tid];
        atomicAdd(&g_sum[b * H_ + tid], t);
    }
}

// ---------------------------------------------------------------------------
// Kernel C1: gated -> shift -> pow, written UNNORMALIZED into d_out + one
// block atomic of the pow-sum. 2 independent float4 groups/thread for MLP.
// ---------------------------------------------------------------------------
__global__ __launch_bounds__(256) void kf1(const float* __restrict__ prev,
                                           float* __restrict__ out) {
    __shared__ float sred[8];
    int bh = blockIdx.y;
    int tid = threadIdx.x;
    int lane = tid & 31;
    int i0 = blockIdx.x * 512 + tid;        // float4 index, group A
    int i1 = i0 + 256;                      // group B

    const float* hp = &g_hp[bh * 8];
    float gate = hp[0], sh0 = hp[1], sh1 = hp[2], sh2 = hp[3], gamma = hp[4];
    float a = gate / g_sum[bh];
    float om = 1.f - gate;

    size_t base = (size_t)bh * N_;
    const __half* e = g_ebuf + base;
    const __half2* e2 = (const __half2*)e;
    const float4* p4 = (const float4*)(prev + base);

    // front-batched loads (MLP 4+)
    float4 pA = p4[i0];
    float4 pB = p4[i1];
    float2 eA0 = __half22float2(e2[2 * i0]);
    float2 eA1 = __half22float2(e2[2 * i0 + 1]);
    float2 eB0 = __half22float2(e2[2 * i1]);
    float2 eB1 = __half22float2(e2[2 * i1 + 1]);

    // boundary-lane halo loads (predicated, issued early)
    int nlA = (4 * i0 + N_ - 1) & (N_ - 1), nrA = (4 * i0 + 4) & (N_ - 1);
    int nlB = (4 * i1 + N_ - 1) & (N_ - 1), nrB = (4 * i1 + 4) & (N_ - 1);
    float haloA = 0.f, haloB = 0.f;
    if (lane == 0) {
        haloA = fmaf(a, __half2float(e[nlA]), om * prev[base + nlA]);
        haloB = fmaf(a, __half2float(e[nlB]), om * prev[base + nlB]);
    } else if (lane == 31) {
        haloA = fmaf(a, __half2float(e[nrA]), om * prev[base + nrA]);
        haloB = fmaf(a, __half2float(e[nrB]), om * prev[base + nrB]);
    }

    float4 gA, gB;
    gA.x = fmaf(a, eA0.x, om * pA.x); gA.y = fmaf(a, eA0.y, om * pA.y);
    gA.z = fmaf(a, eA1.x, om * pA.z); gA.w = fmaf(a, eA1.y, om * pA.w);
    gB.x = fmaf(a, eB0.x, om * pB.x); gB.y = fmaf(a, eB0.y, om * pB.y);
    gB.z = fmaf(a, eB1.x, om * pB.z); gB.w = fmaf(a, eB1.y, om * pB.w);

    float leftA = __shfl_up_sync(0xffffffffu, gA.w, 1);
    float rightA = __shfl_down_sync(0xffffffffu, gA.x, 1);
    float leftB = __shfl_up_sync(0xffffffffu, gB.w, 1);
    float rightB = __shfl_down_sync(0xffffffffu, gB.x, 1);
    if (lane == 0)  { leftA = haloA;  leftB = haloB; }
    if (lane == 31) { rightA = haloA; rightB = haloB; }

    float v0 = fmaf(sh0, leftA, fmaf(sh1, gA.x, sh2 * gA.y));
    float v1 = fmaf(sh0, gA.x, fmaf(sh1, gA.y, sh2 * gA.z));
    float v2 = fmaf(sh0, gA.y, fmaf(sh1, gA.z, sh2 * gA.w));
    float v3 = fmaf(sh0, gA.z, fmaf(sh1, gA.w, sh2 * rightA));
    float u0 = fmaf(sh0, leftB, fmaf(sh1, gB.x, sh2 * gB.y));
    float u1 = fmaf(sh0, gB.x, fmaf(sh1, gB.y, sh2 * gB.z));
    float u2 = fmaf(sh0, gB.y, fmaf(sh1, gB.z, sh2 * gB.w));
    float u3 = fmaf(sh0, gB.z, fmaf(sh1, gB.w, sh2 * rightB));

    float w0 = __powf(v0, gamma), w1 = __powf(v1, gamma);
    float w2 = __powf(v2, gamma), w3 = __powf(v3, gamma);
    float x0 = __powf(u0, gamma), x1 = __powf(u1, gamma);
    float x2 = __powf(u2, gamma), x3 = __powf(u3, gamma);

    float4* o4 = (float4*)(out + base);
    o4[i0] = make_float4(w0, w1, w2, w3);
    o4[i1] = make_float4(x0, x1, x2, x3);

    float ls = ((w0 + w1) + (w2 + w3)) + ((x0 + x1) + (x2 + x3));
    #pragma unroll
    for (int o = 16; o; o >>= 1) ls += __shfl_xor_sync(0xffffffffu, ls, o);
    if (lane == 0) sred[tid >> 5] = ls;
    __syncthreads();
    if (tid == 0) {
        float t = 0.f;
        #pragma unroll
        for (int w = 0; w < 8; w++) t += sred[w];
        atomicAdd(&g_psum[bh], t);
    }
}

// ---------------------------------------------------------------------------
// Kernel C2: in-place scale of d_out (reads mostly hit L2 dirty lines).
// ---------------------------------------------------------------------------
__global__ __launch_bounds__(256) void kf2(float* __restrict__ out) {
    int gid = blockIdx.x * 256 + threadIdx.x;
    int i0 = gid * 2;                   // float4 index; bh = i0 >> 12
    float invT = 1.f / (g_psum[i0 >> 12] + 1e-6f);
    float4* o4 = (float4*)out;
    float4 x = o4[i0], y = o4[i0 + 1];
    x.x *= invT; x.y *= invT; x.z *= invT; x.w *= invT;
    y.x *= invT; y.y *= invT; y.z *= invT; y.w *= invT;
    o4[i0] = x; o4[i0 + 1] = y;
}

// ---------------------------------------------------------------------------
extern "C" void kernel_launch(void* const* d_in, const int* in_sizes, int n_in,
                              void* d_out, int out_size) {
    const float* cs   = (const float*)d_in[0];
    const float* prev = (const float*)d_in[1];
    const float* mem  = (const float*)d_in[2];
    const float* Wr   = (const float*)d_in[3];
    const float* br   = (const float*)d_in[4];
    float* out = (float*)d_out;

    static int inited = 0;
    if (!inited) {
        cudaFuncSetAttribute(kparams, cudaFuncAttributeMaxDynamicSharedMemorySize,
                             (BT + RT) * 256 * 16);
        cudaFuncSetAttribute(kdots, cudaFuncAttributeMaxDynamicSharedMemorySize,
                             256 * 17 * 16);
        inited = 1;
    }

    kparams<<<dim3(R_ / RT, B_ / BT), 256, (BT + RT) * 256 * 16>>>(cs, Wr, br);
    kderive<<<(B_ * H_) / 8, 256>>>();
    kdots<<<dim3(N_ / 256, B_), 256, 256 * 17 * 16>>>(mem);
    kf1<<<dim3(N_ / 2048, B_ * H_), 256>>>(prev, out);
    kf2<<<(B_ * H_ * N_ / 4) / 512, 256>>>(out);
}

// round 5
// speedup vs baseline: 1.5534x; 1.0917x over previous
#include <cuda_runtime.h>
#include <cuda_fp16.h>
#include <math.h>

#define B_ 64
#define H_ 4
#define N_ 16384
#define W_ 64
#define D_ 1024
#define P_ 70
#define R_ 280
#define BT 8
#define RT 10
#define ROWS_PB 512   // rows per kdots block

// Scratch (device globals: allocation-free rule)
__device__ float  g_params[B_ * R_];     // raw GEMM output
__device__ __half g_ebuf[B_ * H_ * N_];  // exp(beta*cos_sim), fp16, 8 MB
__device__ float  g_kv[B_ * H_ * W_];    // key * beta / ||key||
__device__ float  g_hp[B_ * H_ * 8];     // gate, sh0, sh1, sh2, gamma
__device__ float  g_sum[B_ * H_];        // softmax denominators (atomic)
__device__ float  g_psum[B_ * H_];       // pow-sharpen denominators (atomic)

__device__ __forceinline__ float softplusf(float x) {
    return x > 20.f ? x : log1pf(__expf(x));
}

// ---------------------------------------------------------------------------
// Kernel A: tiled GEMM
// ---------------------------------------------------------------------------
__global__ __launch_bounds__(256) void kparams(const float* __restrict__ cs,
                                               const float* __restrict__ Wr,
                                               const float* __restrict__ br) {
    extern __shared__ float4 dynp[];
    float4* scs = dynp;
    float4* sw  = dynp + BT * 256;
    int rt = blockIdx.x, bt = blockIdx.y;
    int tid = threadIdx.x;

    const float4* gcs = (const float4*)cs + (size_t)bt * BT * 256;
    #pragma unroll
    for (int i = 0; i < BT; i++) scs[i * 256 + tid] = gcs[i * 256 + tid];
    const float4* gw = (const float4*)Wr + (size_t)rt * RT * 256;
    #pragma unroll
    for (int i = 0; i < RT; i++) sw[i * 256 + tid] = gw[i * 256 + tid];
    __syncthreads();

    int w = tid >> 5, l = tid & 31;
    const float4* a = scs + w * 256;
    #pragma unroll
    for (int rl = 0; rl < RT; rl++) {
        const float4* bv = sw + rl * 256;
        float4 acc = make_float4(0.f, 0.f, 0.f, 0.f);
        #pragma unroll
        for (int j = 0; j < 8; j++) {
            float4 x = a[j * 32 + l], y = bv[j * 32 + l];
            acc.x = fmaf(x.x, y.x, acc.x);
            acc.y = fmaf(x.y, y.y, acc.y);
            acc.z = fmaf(x.z, y.z, acc.z);
            acc.w = fmaf(x.w, y.w, acc.w);
        }
        float s = (acc.x + acc.y) + (acc.z + acc.w);
        #pragma unroll
        for (int o = 16; o; o >>= 1) s += __shfl_xor_sync(0xffffffffu, s, o);
        if (l == 0) {
            int r = rt * RT + rl;
            g_params[(bt * BT + w) * R_ + r] = s + br[r];
        }
    }
}

// ---------------------------------------------------------------------------
// Kernel A2: one warp per (b,h): key norm + activations.
// ---------------------------------------------------------------------------
__global__ __launch_bounds__(256) void kderive() {
    int gw = (blockIdx.x * 256 + threadIdx.x) >> 5;
    int l = threadIdx.x & 31;
    int b = gw >> 2, h = gw & 3;
    const float* ps = &g_params[b * R_ + h * P_];
    float v0 = ps[l], v1 = ps[l + 32];
    float v2 = (l < 6) ? ps[l + 64] : 0.f;

    float kn2 = fmaf(v0, v0, v1 * v1);
    #pragma unroll
    for (int o = 16; o; o >>= 1) kn2 += __shfl_xor_sync(0xffffffffu, kn2, o);

    float p64 = __shfl_sync(0xffffffffu, v2, 0);
    float p65 = __shfl_sync(0xffffffffu, v2, 1);
    float p66 = __shfl_sync(0xffffffffu, v2, 2);
    float p67 = __shfl_sync(0xffffffffu, v2, 3);
    float p68 = __shfl_sync(0xffffffffu, v2, 4);
    float p69 = __shfl_sync(0xffffffffu, v2, 5);

    float beta = softplusf(p64);
    float scale = beta / fmaxf(sqrtf(kn2), 1e-8f);
    g_kv[gw * W_ + l]      = v0 * scale;
    g_kv[gw * W_ + 32 + l] = v1 * scale;

    if (l == 0) {
        float gate = 1.f / (1.f + __expf(-p65));
        float m = fmaxf(p66, fmaxf(p67, p68));
        float e0 = __expf(p66 - m), e1 = __expf(p67 - m), e2 = __expf(p68 - m);
        float si = 1.f / (e0 + e1 + e2);
        g_hp[gw * 8 + 0] = gate;
        g_hp[gw * 8 + 1] = e0 * si;
        g_hp[gw * 8 + 2] = e1 * si;
        g_hp[gw * 8 + 3] = e2 * si;
        g_hp[gw * 8 + 4] = 1.f + softplusf(p69);
        g_sum[gw] = 0.f;
        g_psum[gw] = 0.f;
    }
}

// ---------------------------------------------------------------------------
// Kernel B: stream memory once, NO transpose tile. 8 lanes per row, keys in
// registers, segmented shfl reduction. Raw (ssq,d0..3) stashed in tiny smem;
// packed epilogue does rsqrt+exp on all lanes, fp16 stage, coalesced stores.
// ---------------------------------------------------------------------------
__global__ __launch_bounds__(256) void kdots(const float* __restrict__ mem) {
    __shared__ float sraw[ROWS_PB * 5];      // [row][ssq,d0,d1,d2,d3]
    __shared__ __half se[H_ * ROWS_PB];      // staged e values
    __shared__ float sred[32];
    int b = blockIdx.y;
    int n0 = blockIdx.x * ROWS_PB;
    int tid = threadIdx.x;
    int w = tid >> 5, l = tid & 31;
    int c = l & 7;                           // float4 component pair base
    int sub = l >> 3;                        // row-within-quad (0..3)

    // keys in registers: head h needs float4 c and c+8
    const float4* kvp = (const float4*)(g_kv + b * (H_ * W_));
    float4 k0a = kvp[c],      k0b = kvp[c + 8];
    float4 k1a = kvp[16 + c], k1b = kvp[16 + c + 8];
    float4 k2a = kvp[32 + c], k2b = kvp[32 + c + 8];
    float4 k3a = kvp[48 + c], k3b = kvp[48 + c + 8];

    const float4* src = (const float4*)(mem + ((size_t)b * N_ + n0) * W_);

    #pragma unroll 4
    for (int i = 0; i < 16; i++) {
        int r = w * 64 + i * 4 + sub;        // row within block chunk
        const float4* rp = src + r * 16;
        float4 ma = rp[c];
        float4 mb = rp[c + 8];

        float ssq, d0, d1, d2, d3;
        ssq = fmaf(ma.x, ma.x, ma.y * ma.y);
        ssq = fmaf(ma.z, ma.z, ssq); ssq = fmaf(ma.w, ma.w, ssq);
        ssq = fmaf(mb.x, mb.x, ssq); ssq = fmaf(mb.y, mb.y, ssq);
        ssq = fmaf(mb.z, mb.z, ssq); ssq = fmaf(mb.w, mb.w, ssq);
        d0 = fmaf(k0a.x, ma.x, k0a.y * ma.y);
        d0 = fmaf(k0a.z, ma.z, d0); d0 = fmaf(k0a.w, ma.w, d0);
        d0 = fmaf(k0b.x, mb.x, d0); d0 = fmaf(k0b.y, mb.y, d0);
        d0 = fmaf(k0b.z, mb.z, d0); d0 = fmaf(k0b.w, mb.w, d0);
        d1 = fmaf(k1a.x, ma.x, k1a.y * ma.y);
        d1 = fmaf(k1a.z, ma.z, d1); d1 = fmaf(k1a.w, ma.w, d1);
        d1 = fmaf(k1b.x, mb.x, d1); d1 = fmaf(k1b.y, mb.y, d1);
        d1 = fmaf(k1b.z, mb.z, d1); d1 = fmaf(k1b.w, mb.w, d1);
        d2 = fmaf(k2a.x, ma.x, k2a.y * ma.y);
        d2 = fmaf(k2a.z, ma.z, d2); d2 = fmaf(k2a.w, ma.w, d2);
        d2 = fmaf(k2b.x, mb.x, d2); d2 = fmaf(k2b.y, mb.y, d2);
        d2 = fmaf(k2b.z, mb.z, d2); d2 = fmaf(k2b.w, mb.w, d2);
        d3 = fmaf(k3a.x, ma.x, k3a.y * ma.y);
        d3 = fmaf(k3a.z, ma.z, d3); d3 = fmaf(k3a.w, ma.w, d3);
        d3 = fmaf(k3b.x, mb.x, d3); d3 = fmaf(k3b.y, mb.y, d3);
        d3 = fmaf(k3b.z, mb.z, d3); d3 = fmaf(k3b.w, mb.w, d3);

        #pragma unroll
        for (int o = 1; o < 8; o <<= 1) {
            ssq += __shfl_xor_sync(0xffffffffu, ssq, o);
            d0  += __shfl_xor_sync(0xffffffffu, d0, o);
            d1  += __shfl_xor_sync(0xffffffffu, d1, o);
            d2  += __shfl_xor_sync(0xffffffffu, d2, o);
            d3  += __shfl_xor_sync(0xffffffffu, d3, o);
        }
        if (c == 0) {
            float* dst = &sraw[r * 5];
            dst[0] = ssq; dst[1] = d0; dst[2] = d1; dst[3] = d2; dst[4] = d3;
        }
    }
    __syncthreads();

    // packed epilogue: 2048 (h,row) exps over 256 threads; stride-5 LDS is
    // conflict-free (gcd(5,32)=1)
    float s0 = 0.f, s1 = 0.f, s2 = 0.f, s3 = 0.f;
    #pragma unroll
    for (int p = 0; p < 8; p++) {
        int idx = p * 256 + tid;
        int row = idx & (ROWS_PB - 1);
        int h = idx >> 9;
        float ssq = sraw[row * 5];
        float d = sraw[row * 5 + 1 + h];
        float inv = rsqrtf(fmaxf(ssq, 1e-16f));
        __half hv = __float2half(__expf(d * inv));
        se[h * ROWS_PB + row] = hv;
        float e = __half2float(hv);
        if (h == 0) s0 += e; else if (h == 1) s1 += e;
        else if (h == 2) s2 += e; else s3 += e;
    }
    #pragma unroll
    for (int o = 16; o; o >>= 1) {
        s0 += __shfl_xor_sync(0xffffffffu, s0, o);
        s1 += __shfl_xor_sync(0xffffffffu, s1, o);
        s2 += __shfl_xor_sync(0xffffffffu, s2, o);
        s3 += __shfl_xor_sync(0xffffffffu, s3, o);
    }
    if (l == 0) {
        sred[w * 4 + 0] = s0; sred[w * 4 + 1] = s1;
        sred[w * 4 + 2] = s2; sred[w * 4 + 3] = s3;
    }
    __syncthreads();

    // coalesced stores: 512 uint2 (4 halves each), 2 per thread
    const uint2* sep = (const uint2*)se;
    #pragma unroll
    for (int q = 0; q < 2; q++) {
        int j = q * 256 + tid;               // 0..511
        int h = j >> 7, off = j & 127;       // 128 uint2 per head
        uint2* dst = (uint2*)(g_ebuf + ((size_t)(b * H_ + h)) * N_ + n0);
        dst[off] = sep[j];
    }
    if (tid < 4) {
        float t = 0.f;
        #pragma unroll
        for (int wp = 0; wp < 8; wp++) t += sred[wp * 4 + tid];
        atomicAdd(&g_sum[b * H_ + tid], t);
    }
}

// ---------------------------------------------------------------------------
// Kernel C1: gated -> shift -> pow, UNNORMALIZED into d_out + pow-sum atomic.
// ---------------------------------------------------------------------------
__global__ __launch_bounds__(256) void kf1(const float* __restrict__ prev,
                                           float* __restrict__ out) {
    __shared__ float sred[8];
    int bh = blockIdx.y;
    int tid = threadIdx.x;
    int lane = tid & 31;
    int i0 = blockIdx.x * 512 + tid;
    int i1 = i0 + 256;

    const float* hp = &g_hp[bh * 8];
    float gate = hp[0], sh0 = hp[1], sh1 = hp[2], sh2 = hp[3], gamma = hp[4];
    float a = gate / g_sum[bh];
    float om = 1.f - gate;

    size_t base = (size_t)bh * N_;
    const __half* e = g_ebuf + base;
    const __half2* e2 = (const __half2*)e;
    const float4* p4 = (const float4*)(prev + base);

    float4 pA = p4[i0];
    float4 pB = p4[i1];
    float2 eA0 = __half22float2(e2[2 * i0]);
    float2 eA1 = __half22float2(e2[2 * i0 + 1]);
    float2 eB0 = __half22float2(e2[2 * i1]);
    float2 eB1 = __half22float2(e2[2 * i1 + 1]);

    int nlA = (4 * i0 + N_ - 1) & (N_ - 1), nrA = (4 * i0 + 4) & (N_ - 1);
    int nlB = (4 * i1 + N_ - 1) & (N_ - 1), nrB = (4 * i1 + 4) & (N_ - 1);
    float haloA = 0.f, haloB = 0.f;
    if (lane == 0) {
        haloA = fmaf(a, __half2float(e[nlA]), om * prev[base + nlA]);
        haloB = fmaf(a, __half2float(e[nlB]), om * prev[base + nlB]);
    } else if (lane == 31) {
        haloA = fmaf(a, __half2float(e[nrA]), om * prev[base + nrA]);
        haloB = fmaf(a, __half2float(e[nrB]), om * prev[base + nrB]);
    }

    float4 gA, gB;
    gA.x = fmaf(a, eA0.x, om * pA.x); gA.y = fmaf(a, eA0.y, om * pA.y);
    gA.z = fmaf(a, eA1.x, om * pA.z); gA.w = fmaf(a, eA1.y, om * pA.w);
    gB.x = fmaf(a, eB0.x, om * pB.x); gB.y = fmaf(a, eB0.y, om * pB.y);
    gB.z = fmaf(a, eB1.x, om * pB.z); gB.w = fmaf(a, eB1.y, om * pB.w);

    float leftA = __shfl_up_sync(0xffffffffu, gA.w, 1);
    float rightA = __shfl_down_sync(0xffffffffu, gA.x, 1);
    float leftB = __shfl_up_sync(0xffffffffu, gB.w, 1);
    float rightB = __shfl_down_sync(0xffffffffu, gB.x, 1);
    if (lane == 0)  { leftA = haloA;  leftB = haloB; }
    if (lane == 31) { rightA = haloA; rightB = haloB; }

    float v0 = fmaf(sh0, leftA, fmaf(sh1, gA.x, sh2 * gA.y));
    float v1 = fmaf(sh0, gA.x, fmaf(sh1, gA.y, sh2 * gA.z));
    float v2 = fmaf(sh0, gA.y, fmaf(sh1, gA.z, sh2 * gA.w));
    float v3 = fmaf(sh0, gA.z, fmaf(sh1, gA.w, sh2 * rightA));
    float u0 = fmaf(sh0, leftB, fmaf(sh1, gB.x, sh2 * gB.y));
    float u1 = fmaf(sh0, gB.x, fmaf(sh1, gB.y, sh2 * gB.z));
    float u2 = fmaf(sh0, gB.y, fmaf(sh1, gB.z, sh2 * gB.w));
    float u3 = fmaf(sh0, gB.z, fmaf(sh1, gB.w, sh2 * rightB));

    float w0 = __powf(v0, gamma), w1 = __powf(v1, gamma);
    float w2 = __powf(v2, gamma), w3 = __powf(v3, gamma);
    float x0 = __powf(u0, gamma), x1 = __powf(u1, gamma);
    float x2 = __powf(u2, gamma), x3 = __powf(u3, gamma);

    float4* o4 = (float4*)(out + base);
    o4[i0] = make_float4(w0, w1, w2, w3);
    o4[i1] = make_float4(x0, x1, x2, x3);

    float ls = ((w0 + w1) + (w2 + w3)) + ((x0 + x1) + (x2 + x3));
    #pragma unroll
    for (int o = 16; o; o >>= 1) ls += __shfl_xor_sync(0xffffffffu, ls, o);
    if (lane == 0) sred[tid >> 5] = ls;
    __syncthreads();
    if (tid == 0) {
        float t = 0.f;
        #pragma unroll
        for (int w = 0; w < 8; w++) t += sred[w];
        atomicAdd(&g_psum[bh], t);
    }
}

// ---------------------------------------------------------------------------
// Kernel C2: in-place scale of d_out (reads mostly L2 dirty lines).
// ---------------------------------------------------------------------------
__global__ __launch_bounds__(256) void kf2(float* __restrict__ out) {
    int gid = blockIdx.x * 256 + threadIdx.x;
    int i0 = gid * 2;
    float invT = 1.f / (g_psum[i0 >> 12] + 1e-6f);
    float4* o4 = (float4*)out;
    float4 x = o4[i0], y = o4[i0 + 1];
    x.x *= invT; x.y *= invT; x.z *= invT; x.w *= invT;
    y.x *= invT; y.y *= invT; y.z *= invT; y.w *= invT;
    o4[i0] = x; o4[i0 + 1] = y;
}

// ---------------------------------------------------------------------------
extern "C" void kernel_launch(void* const* d_in, const int* in_sizes, int n_in,
                              void* d_out, int out_size) {
    const float* cs   = (const float*)d_in[0];
    const float* prev = (const float*)d_in[1];
    const float* mem  = (const float*)d_in[2];
    const float* Wr   = (const float*)d_in[3];
    const float* br   = (const float*)d_in[4];
    float* out = (float*)d_out;

    static int inited = 0;
    if (!inited) {
        cudaFuncSetAttribute(kparams, cudaFuncAttributeMaxDynamicSharedMemorySize,
                             (BT + RT) * 256 * 16);
        inited = 1;
    }

    kparams<<<dim3(R_ / RT, B_ / BT), 256, (BT + RT) * 256 * 16>>>(cs, Wr, br);
    kderive<<<(B_ * H_) / 8, 256>>>();
    kdots<<<dim3(N_ / ROWS_PB, B_), 256>>>(mem);
    kf1<<<dim3(N_ / 2048, B_ * H_), 256>>>(prev, out);
    kf2<<<(B_ * H_ * N_ / 4) / 512, 256>>>(out);
}

// round 7
// speedup vs baseline: 1.6320x; 1.0506x over previous
#include <cuda_runtime.h>
#include <cuda_fp16.h>
#include <math.h>

#define B_ 64
#define H_ 4
#define N_ 16384
#define W_ 64
#define D_ 1024
#define P_ 70
#define ROWS_PB 512   // rows per kdots block

// Scratch (device globals: allocation-free rule)
__device__ __half g_ebuf[B_ * H_ * N_];  // exp(beta*cos_sim), fp16, 8 MB
__device__ float  g_kv[B_ * H_ * W_];    // key * beta / ||key||
__device__ float  g_hp[B_ * H_ * 8];     // gate, sh0, sh1, sh2, gamma
__device__ float  g_sum[B_ * H_];        // softmax denominators (atomic)
__device__ float  g_psum[B_ * H_];       // pow-sharpen denominators (atomic)

__device__ __forceinline__ float softplusf(float x) {
    return x > 20.f ? x : log1pf(__expf(x));
}

// ---------------------------------------------------------------------------
// Kernel A: fused params GEMV + activations. One block per (b,h).
// ---------------------------------------------------------------------------
__global__ __launch_bounds__(256) void kparams(const float* __restrict__ cs,
                                               const float* __restrict__ Wr,
                                               const float* __restrict__ br) {
    int bh = blockIdx.x;
    int b = bh >> 2, h = bh & 3;
    __shared__ float4 scs[256];
    __shared__ float ps[P_];
    int tid = threadIdx.x;
    int w = tid >> 5, l = tid & 31;

    scs[tid] = ((const float4*)(cs + (size_t)b * D_))[tid];
    __syncthreads();

    for (int p = w; p < P_; p += 8) {
        const float4* Wrow = (const float4*)(Wr + (size_t)(h * P_ + p) * D_);
        float4 acc = make_float4(0.f, 0.f, 0.f, 0.f);
        #pragma unroll
        for (int j = 0; j < 8; j++) {
            float4 x = Wrow[j * 32 + l];
            float4 y = scs[j * 32 + l];
            acc.x = fmaf(x.x, y.x, acc.x);
            acc.y = fmaf(x.y, y.y, acc.y);
            acc.z = fmaf(x.z, y.z, acc.z);
            acc.w = fmaf(x.w, y.w, acc.w);
        }
        float s = (acc.x + acc.y) + (acc.z + acc.w);
        #pragma unroll
        for (int o = 16; o; o >>= 1) s += __shfl_xor_sync(0xffffffffu, s, o);
        if (l == 0) ps[p] = s + br[h * P_ + p];
    }
    __syncthreads();

    if (w == 0) {
        float v0 = ps[l], v1 = ps[l + 32];
        float kn2 = fmaf(v0, v0, v1 * v1);
        #pragma unroll
        for (int o = 16; o; o >>= 1) kn2 += __shfl_xor_sync(0xffffffffu, kn2, o);

        float beta = softplusf(ps[W_]);
        float scale = beta / fmaxf(sqrtf(kn2), 1e-8f);
        g_kv[bh * W_ + l]      = v0 * scale;
        g_kv[bh * W_ + 32 + l] = v1 * scale;

        if (l == 0) {
            float gate = 1.f / (1.f + __expf(-ps[W_ + 1]));
            float m = fmaxf(ps[W_ + 2], fmaxf(ps[W_ + 3], ps[W_ + 4]));
            float e0 = __expf(ps[W_ + 2] - m);
            float e1 = __expf(ps[W_ + 3] - m);
            float e2 = __expf(ps[W_ + 4] - m);
            float si = 1.f / (e0 + e1 + e2);
            g_hp[bh * 8 + 0] = gate;
            g_hp[bh * 8 + 1] = e0 * si;
            g_hp[bh * 8 + 2] = e1 * si;
            g_hp[bh * 8 + 3] = e2 * si;
            g_hp[bh * 8 + 4] = 1.f + softplusf(ps[W_ + 5]);
            g_sum[bh] = 0.f;
            g_psum[bh] = 0.f;
        }
    }
}

// ---------------------------------------------------------------------------
// Kernel B: stream memory once. 4 lanes per row (8 rows/warp-iter), keys in
// registers; only 2 butterfly rounds per row group (10 shfl / 8 rows).
// ---------------------------------------------------------------------------
__global__ __launch_bounds__(256, 2) void kdots(const float* __restrict__ mem) {
    __shared__ float sraw[ROWS_PB * 5];      // [row][ssq,d0,d1,d2,d3]
    __shared__ __half se[H_ * ROWS_PB];      // staged e values
    __shared__ float sred[32];
    int b = blockIdx.y;
    int n0 = blockIdx.x * ROWS_PB;
    int tid = threadIdx.x;
    int w = tid >> 5, l = tid & 31;
    int c = l & 3;                           // quarter-segment within row
    int sub = l >> 2;                        // row-within-octet (0..7)

    // keys: head h quarter c = float4 indices {c, c+4, c+8, c+12}
    const float4* kvp = (const float4*)(g_kv + b * (H_ * W_));
    float4 kk[H_][4];
    #pragma unroll
    for (int h = 0; h < H_; h++)
        #pragma unroll
        for (int j = 0; j < 4; j++)
            kk[h][j] = kvp[h * 16 + c + j * 4];

    const float4* src = (const float4*)(mem + ((size_t)b * N_ + n0) * W_);

    #pragma unroll 2
    for (int i = 0; i < 8; i++) {
        int r = w * 64 + i * 8 + sub;
        const float4* rp = src + r * 16;
        float4 mm[4];
        #pragma unroll
        for (int j = 0; j < 4; j++) mm[j] = rp[c + j * 4];

        float ssq = 0.f, d0 = 0.f, d1 = 0.f, d2 = 0.f, d3 = 0.f;
        #pragma unroll
        for (int j = 0; j < 4; j++) {
            float4 m = mm[j];
            ssq = fmaf(m.x, m.x, ssq); ssq = fmaf(m.y, m.y, ssq);
            ssq = fmaf(m.z, m.z, ssq); ssq = fmaf(m.w, m.w, ssq);
            float4 a0 = kk[0][j];
            d0 = fmaf(a0.x, m.x, d0); d0 = fmaf(a0.y, m.y, d0);
            d0 = fmaf(a0.z, m.z, d0); d0 = fmaf(a0.w, m.w, d0);
            float4 a1 = kk[1][j];
            d1 = fmaf(a1.x, m.x, d1); d1 = fmaf(a1.y, m.y, d1);
            d1 = fmaf(a1.z, m.z, d1); d1 = fmaf(a1.w, m.w, d1);
            float4 a2 = kk[2][j];
            d2 = fmaf(a2.x, m.x, d2); d2 = fmaf(a2.y, m.y, d2);
            d2 = fmaf(a2.z, m.z, d2); d2 = fmaf(a2.w, m.w, d2);
            float4 a3 = kk[3][j];
            d3 = fmaf(a3.x, m.x, d3); d3 = fmaf(a3.y, m.y, d3);
            d3 = fmaf(a3.z, m.z, d3); d3 = fmaf(a3.w, m.w, d3);
        }

        #pragma unroll
        for (int o = 2; o; o >>= 1) {
            ssq += __shfl_xor_sync(0xffffffffu, ssq, o);
            d0  += __shfl_xor_sync(0xffffffffu, d0, o);
            d1  += __shfl_xor_sync(0xffffffffu, d1, o);
            d2  += __shfl_xor_sync(0xffffffffu, d2, o);
            d3  += __shfl_xor_sync(0xffffffffu, d3, o);
        }
        if (c == 0) {
            float* dst = &sraw[r * 5];
            dst[0] = ssq; dst[1] = d0; dst[2] = d1; dst[3] = d2; dst[4] = d3;
        }
    }
    __syncthreads();

    // packed epilogue: 2048 (h,row) exps over 256 threads; stride-5 LDS
    // conflict-free (gcd(5,32)=1)
    float s0 = 0.f, s1 = 0.f, s2 = 0.f, s3 = 0.f;
    #pragma unroll
    for (int p = 0; p < 8; p++) {
        int idx = p * 256 + tid;
        int row = idx & (ROWS_PB - 1);
        int h = idx >> 9;
        float ssq = sraw[row * 5];
        float d = sraw[row * 5 + 1 + h];
        float inv = rsqrtf(fmaxf(ssq, 1e-16f));
        __half hv = __float2half(__expf(d * inv));
        se[h * ROWS_PB + row] = hv;
        float e = __half2float(hv);
        if (h == 0) s0 += e; else if (h == 1) s1 += e;
        else if (h == 2) s2 += e; else s3 += e;
    }
    #pragma unroll
    for (int o = 16; o; o >>= 1) {
        s0 += __shfl_xor_sync(0xffffffffu, s0, o);
        s1 += __shfl_xor_sync(0xffffffffu, s1, o);
        s2 += __shfl_xor_sync(0xffffffffu, s2, o);
        s3 += __shfl_xor_sync(0xffffffffu, s3, o);
    }
    if (l == 0) {
        sred[w * 4 + 0] = s0; sred[w * 4 + 1] = s1;
        sred[w * 4 + 2] = s2; sred[w * 4 + 3] = s3;
    }
    __syncthreads();

    const uint2* sep = (const uint2*)se;
    #pragma unroll
    for (int q = 0; q < 2; q++) {
        int j = q * 256 + tid;
        int h = j >> 7, off = j & 127;
        uint2* dst = (uint2*)(g_ebuf + ((size_t)(b * H_ + h)) * N_ + n0);
        dst[off] = sep[j];
    }
    if (tid < 4) {
        float t = 0.f;
        #pragma unroll
        for (int wp = 0; wp < 8; wp++) t += sred[wp * 4 + tid];
        atomicAdd(&g_sum[b * H_ + tid], t);
    }
}

// ---------------------------------------------------------------------------
// Kernel C1: gated -> shift -> pow, UNNORMALIZED into d_out + pow-sum atomic.
// (MUFU-bound near its ~8us floor.)
// ---------------------------------------------------------------------------
__global__ __launch_bounds__(256) void kf1(const float* __restrict__ prev,
                                           float* __restrict__ out) {
    __shared__ float sred[8];
    int bh = blockIdx.y;
    int tid = threadIdx.x;
    int lane = tid & 31;
    int i0 = blockIdx.x * 512 + tid;
    int i1 = i0 + 256;

    const float* hp = &g_hp[bh * 8];
    float gate = hp[0], sh0 = hp[1], sh1 = hp[2], sh2 = hp[3], gamma = hp[4];
    float a = gate / g_sum[bh];
    float om = 1.f - gate;

    size_t base = (size_t)bh * N_;
    const __half* e = g_ebuf + base;
    const __half2* e2 = (const __half2*)e;
    const float4* p4 = (const float4*)(prev + base);

    float4 pA = p4[i0];
    float4 pB = p4[i1];
    float2 eA0 = __half22float2(e2[2 * i0]);
    float2 eA1 = __half22float2(e2[2 * i0 + 1]);
    float2 eB0 = __half22float2(e2[2 * i1]);
    float2 eB1 = __half22float2(e2[2 * i1 + 1]);

    int nlA = (4 * i0 + N_ - 1) & (N_ - 1), nrA = (4 * i0 + 4) & (N_ - 1);
    int nlB = (4 * i1 + N_ - 1) & (N_ - 1), nrB = (4 * i1 + 4) & (N_ - 1);
    float haloA = 0.f, haloB = 0.f;
    if (lane == 0) {
        haloA = fmaf(a, __half2float(e[nlA]), om * prev[base + nlA]);
        haloB = fmaf(a, __half2float(e[nlB]), om * prev[base + nlB]);
    } else if (lane == 31) {
        haloA = fmaf(a, __half2float(e[nrA]), om * prev[base + nrA]);
        haloB = fmaf(a, __half2float(e[nrB]), om * prev[base + nrB]);
    }

    float4 gA, gB;
    gA.x = fmaf(a, eA0.x, om * pA.x); gA.y = fmaf(a, eA0.y, om * pA.y);
    gA.z = fmaf(a, eA1.x, om * pA.z); gA.w = fmaf(a, eA1.y, om * pA.w);
    gB.x = fmaf(a, eB0.x, om * pB.x); gB.y = fmaf(a, eB0.y, om * pB.y);
    gB.z = fmaf(a, eB1.x, om * pB.z); gB.w = fmaf(a, eB1.y, om * pB.w);

    float leftA = __shfl_up_sync(0xffffffffu, gA.w, 1);
    float rightA = __shfl_down_sync(0xffffffffu, gA.x, 1);
    float leftB = __shfl_up_sync(0xffffffffu, gB.w, 1);
    float rightB = __shfl_down_sync(0xffffffffu, gB.x, 1);
    if (lane == 0)  { leftA = haloA;  leftB = haloB; }
    if (lane == 31) { rightA = haloA; rightB = haloB; }

    float v0 = fmaf(sh0, leftA, fmaf(sh1, gA.x, sh2 * gA.y));
    float v1 = fmaf(sh0, gA.x, fmaf(sh1, gA.y, sh2 * gA.z));
    float v2 = fmaf(sh0, gA.y, fmaf(sh1, gA.z, sh2 * gA.w));
    float v3 = fmaf(sh0, gA.z, fmaf(sh1, gA.w, sh2 * rightA));
    float u0 = fmaf(sh0, leftB, fmaf(sh1, gB.x, sh2 * gB.y));
    float u1 = fmaf(sh0, gB.x, fmaf(sh1, gB.y, sh2 * gB.z));
    float u2 = fmaf(sh0, gB.y, fmaf(sh1, gB.z, sh2 * gB.w));
    float u3 = fmaf(sh0, gB.z, fmaf(sh1, gB.w, sh2 * rightB));

    float w0 = __powf(v0, gamma), w1 = __powf(v1, gamma);
    float w2 = __powf(v2, gamma), w3 = __powf(v3, gamma);
    float x0 = __powf(u0, gamma), x1 = __powf(u1, gamma);
    float x2 = __powf(u2, gamma), x3 = __powf(u3, gamma);

    float4* o4 = (float4*)(out + base);
    o4[i0] = make_float4(w0, w1, w2, w3);
    o4[i1] = make_float4(x0, x1, x2, x3);

    float ls = ((w0 + w1) + (w2 + w3)) + ((x0 + x1) + (x2 + x3));
    #pragma unroll
    for (int o = 16; o; o >>= 1) ls += __shfl_xor_sync(0xffffffffu, ls, o);
    if (lane == 0) sred[tid >> 5] = ls;
    __syncthreads();
    if (tid == 0) {
        float t = 0.f;
        #pragma unroll
        for (int w = 0; w < 8; w++) t += sred[w];
        atomicAdd(&g_psum[bh], t);
    }
}

// ---------------------------------------------------------------------------
// Kernel C2: in-place scale of d_out (reads mostly L2 dirty lines).
// ---------------------------------------------------------------------------
__global__ __launch_bounds__(256) void kf2(float* __restrict__ out) {
    int gid = blockIdx.x * 256 + threadIdx.x;
    int i0 = gid * 2;
    float invT = 1.f / (g_psum[i0 >> 12] + 1e-6f);
    float4* o4 = (float4*)out;
    float4 x = o4[i0], y = o4[i0 + 1];
    x.x *= invT; x.y *= invT; x.z *= invT; x.w *= invT;
    y.x *= invT; y.y *= invT; y.z *= invT; y.w *= invT;
    o4[i0] = x; o4[i0 + 1] = y;
}

// ---------------------------------------------------------------------------
extern "C" void kernel_launch(void* const* d_in, const int* in_sizes, int n_in,
                              void* d_out, int out_size) {
    const float* cs   = (const float*)d_in[0];
    const float* prev = (const float*)d_in[1];
    const float* mem  = (const float*)d_in[2];
    const float* Wr   = (const float*)d_in[3];
    const float* br   = (const float*)d_in[4];
    float* out = (float*)d_out;

    kparams<<<B_ * H_, 256>>>(cs, Wr, br);
    kdots<<<dim3(N_ / ROWS_PB, B_), 256>>>(mem);
    kf1<<<dim3(N_ / 2048, B_ * H_), 256>>>(prev, out);
    kf2<<<(B_ * H_ * N_ / 4) / 512, 256>>>(out);
}

// round 8
// speedup vs baseline: 1.7284x; 1.0590x over previous
#include <cuda_runtime.h>
#include <cuda_fp16.h>
#include <math.h>

#define B_ 64
#define H_ 4
#define N_ 16384
#define W_ 64
#define D_ 1024
#define P_ 70
#define ROWS_PB 512   // rows per kdots block

// Scratch (device globals: allocation-free rule)
__device__ __half g_ebuf[B_ * H_ * N_];  // exp(beta*cos_sim), fp16, 8 MB
__device__ float  g_kv[B_ * H_ * W_];    // key * beta / ||key||
__device__ float  g_hp[B_ * H_ * 8];     // gate, sh0, sh1, sh2, gamma
__device__ float  g_sum[B_ * H_];        // softmax denominators (atomic)

__device__ __forceinline__ float softplusf(float x) {
    return x > 20.f ? x : log1pf(__expf(x));
}

// sm_103a packed f32x2 FMA; operands already live as 64-bit pairs (ulonglong2
// loads) so ptxas emits no packing movs.
__device__ __forceinline__ unsigned long long ff2(unsigned long long a,
                                                  unsigned long long b,
                                                  unsigned long long c) {
    unsigned long long d;
    asm("fma.rn.f32x2 %0, %1, %2, %3;" : "=l"(d) : "l"(a), "l"(b), "l"(c));
    return d;
}
__device__ __forceinline__ float hsum2(unsigned long long v) {
    float x, y;
    asm("mov.b64 {%0, %1}, %2;" : "=f"(x), "=f"(y) : "l"(v));
    return x + y;
}

// ---------------------------------------------------------------------------
// Kernel A: fused params GEMV + activations. One block per (b,h).
// ---------------------------------------------------------------------------
__global__ __launch_bounds__(256) void kparams(const float* __restrict__ cs,
                                               const float* __restrict__ Wr,
                                               const float* __restrict__ br) {
    int bh = blockIdx.x;
    int b = bh >> 2, h = bh & 3;
    __shared__ float4 scs[256];
    __shared__ float ps[P_];
    int tid = threadIdx.x;
    int w = tid >> 5, l = tid & 31;

    scs[tid] = ((const float4*)(cs + (size_t)b * D_))[tid];
    __syncthreads();

    for (int p = w; p < P_; p += 8) {
        const float4* Wrow = (const float4*)(Wr + (size_t)(h * P_ + p) * D_);
        float4 acc = make_float4(0.f, 0.f, 0.f, 0.f);
        #pragma unroll
        for (int j = 0; j < 8; j++) {
            float4 x = Wrow[j * 32 + l];
            float4 y = scs[j * 32 + l];
            acc.x = fmaf(x.x, y.x, acc.x);
            acc.y = fmaf(x.y, y.y, acc.y);
            acc.z = fmaf(x.z, y.z, acc.z);
            acc.w = fmaf(x.w, y.w, acc.w);
        }
        float s = (acc.x + acc.y) + (acc.z + acc.w);
        #pragma unroll
        for (int o = 16; o; o >>= 1) s += __shfl_xor_sync(0xffffffffu, s, o);
        if (l == 0) ps[p] = s + br[h * P_ + p];
    }
    __syncthreads();

    if (w == 0) {
        float v0 = ps[l], v1 = ps[l + 32];
        float kn2 = fmaf(v0, v0, v1 * v1);
        #pragma unroll
        for (int o = 16; o; o >>= 1) kn2 += __shfl_xor_sync(0xffffffffu, kn2, o);

        float beta = softplusf(ps[W_]);
        float scale = beta / fmaxf(sqrtf(kn2), 1e-8f);
        g_kv[bh * W_ + l]      = v0 * scale;
        g_kv[bh * W_ + 32 + l] = v1 * scale;

        if (l == 0) {
            float gate = 1.f / (1.f + __expf(-ps[W_ + 1]));
            float m = fmaxf(ps[W_ + 2], fmaxf(ps[W_ + 3], ps[W_ + 4]));
            float e0 = __expf(ps[W_ + 2] - m);
            float e1 = __expf(ps[W_ + 3] - m);
            float e2 = __expf(ps[W_ + 4] - m);
            float si = 1.f / (e0 + e1 + e2);
            g_hp[bh * 8 + 0] = gate;
            g_hp[bh * 8 + 1] = e0 * si;
            g_hp[bh * 8 + 2] = e1 * si;
            g_hp[bh * 8 + 3] = e2 * si;
            g_hp[bh * 8 + 4] = 1.f + softplusf(ps[W_ + 5]);
            g_sum[bh] = 0.f;
        }
    }
}

// ---------------------------------------------------------------------------
// Kernel B: stream memory once. 4 lanes/row, ulonglong2 loads feeding packed
// FFMA2 (no packing movs) -> FMA pipe at half pressure, DRAM-bound.
// ---------------------------------------------------------------------------
__global__ __launch_bounds__(256, 2) void kdots(const float* __restrict__ mem) {
    __shared__ float sraw[ROWS_PB * 5];      // [row][ssq,d0,d1,d2,d3]
    __shared__ __half se[H_ * ROWS_PB];      // staged e values
    __shared__ float sred[32];
    int b = blockIdx.y;
    int n0 = blockIdx.x * ROWS_PB;
    int tid = threadIdx.x;
    int w = tid >> 5, l = tid & 31;
    int c = l & 3;                           // quarter-segment within row
    int sub = l >> 2;                        // row-within-octet (0..7)

    // keys as packed 64-bit pairs: head h quarter c = indices {c,c+4,c+8,c+12}
    const ulonglong2* kvp = (const ulonglong2*)(g_kv + b * (H_ * W_));
    ulonglong2 kk[H_][4];
    #pragma unroll
    for (int h = 0; h < H_; h++)
        #pragma unroll
        for (int j = 0; j < 4; j++)
            kk[h][j] = kvp[h * 16 + c + j * 4];

    const ulonglong2* src = (const ulonglong2*)(mem + ((size_t)b * N_ + n0) * W_);

    #pragma unroll 2
    for (int i = 0; i < 8; i++) {
        int r = w * 64 + i * 8 + sub;
        const ulonglong2* rp = src + r * 16;
        ulonglong2 mm[4];
        #pragma unroll
        for (int j = 0; j < 4; j++) mm[j] = rp[c + j * 4];

        unsigned long long ssq = 0, d0 = 0, d1 = 0, d2 = 0, d3 = 0;
        #pragma unroll
        for (int j = 0; j < 4; j++) {
            unsigned long long mx = mm[j].x, my = mm[j].y;
            ssq = ff2(mx, mx, ssq);          ssq = ff2(my, my, ssq);
            d0 = ff2(kk[0][j].x, mx, d0);    d0 = ff2(kk[0][j].y, my, d0);
            d1 = ff2(kk[1][j].x, mx, d1);    d1 = ff2(kk[1][j].y, my, d1);
            d2 = ff2(kk[2][j].x, mx, d2);    d2 = ff2(kk[2][j].y, my, d2);
            d3 = ff2(kk[3][j].x, mx, d3);    d3 = ff2(kk[3][j].y, my, d3);
        }

        float fs = hsum2(ssq);
        float f0 = hsum2(d0), f1 = hsum2(d1), f2 = hsum2(d2), f3 = hsum2(d3);
        #pragma unroll
        for (int o = 2; o; o >>= 1) {
            fs += __shfl_xor_sync(0xffffffffu, fs, o);
            f0 += __shfl_xor_sync(0xffffffffu, f0, o);
            f1 += __shfl_xor_sync(0xffffffffu, f1, o);
            f2 += __shfl_xor_sync(0xffffffffu, f2, o);
            f3 += __shfl_xor_sync(0xffffffffu, f3, o);
        }
        if (c == 0) {
            float* dst = &sraw[r * 5];
            dst[0] = fs; dst[1] = f0; dst[2] = f1; dst[3] = f2; dst[4] = f3;
        }
    }
    __syncthreads();

    // packed epilogue: 2048 (h,row) exps over 256 threads; stride-5 LDS
    // conflict-free (gcd(5,32)=1)
    float s0 = 0.f, s1 = 0.f, s2 = 0.f, s3 = 0.f;
    #pragma unroll
    for (int p = 0; p < 8; p++) {
        int idx = p * 256 + tid;
        int row = idx & (ROWS_PB - 1);
        int h = idx >> 9;
        float ssq = sraw[row * 5];
        float d = sraw[row * 5 + 1 + h];
        float inv = rsqrtf(fmaxf(ssq, 1e-16f));
        __half hv = __float2half(__expf(d * inv));
        se[h * ROWS_PB + row] = hv;
        float e = __half2float(hv);
        if (h == 0) s0 += e; else if (h == 1) s1 += e;
        else if (h == 2) s2 += e; else s3 += e;
    }
    #pragma unroll
    for (int o = 16; o; o >>= 1) {
        s0 += __shfl_xor_sync(0xffffffffu, s0, o);
        s1 += __shfl_xor_sync(0xffffffffu, s1, o);
        s2 += __shfl_xor_sync(0xffffffffu, s2, o);
        s3 += __shfl_xor_sync(0xffffffffu, s3, o);
    }
    if (l == 0) {
        sred[w * 4 + 0] = s0; sred[w * 4 + 1] = s1;
        sred[w * 4 + 2] = s2; sred[w * 4 + 3] = s3;
    }
    __syncthreads();

    const uint2* sep = (const uint2*)se;
    #pragma unroll
    for (int q = 0; q < 2; q++) {
        int j = q * 256 + tid;
        int h = j >> 7, off = j & 127;
        uint2* dst = (uint2*)(g_ebuf + ((size_t)(b * H_ + h)) * N_ + n0);
        dst[off] = sep[j];
    }
    if (tid < 4) {
        float t = 0.f;
        #pragma unroll
        for (int wp = 0; wp < 8; wp++) t += sred[wp * 4 + tid];
        atomicAdd(&g_sum[b * H_ + tid], t);
    }
}

// ---------------------------------------------------------------------------
// Kernel C: one (b,h) per block. gated -> shift -> SINGLE pow -> pw in smem
// -> block reduce -> scale & write. Halos for warp edges recomputed from
// global (no second smem array needed).
// ---------------------------------------------------------------------------
__global__ __launch_bounds__(1024, 2) void kfinish(const float* __restrict__ prev,
                                                   float* __restrict__ out) {
    extern __shared__ float spw[];           // N_ unnormalized pw values
    __shared__ float sr[33];
    int bh = blockIdx.x;
    int tid = threadIdx.x;
    int lane = tid & 31;

    const float* hp = &g_hp[bh * 8];
    float gate = hp[0], sh0 = hp[1], sh1 = hp[2], sh2 = hp[3], gamma = hp[4];
    float a = gate / g_sum[bh];
    float om = 1.f - gate;

    size_t base = (size_t)bh * N_;
    const __half* e = g_ebuf + base;
    const __half2* e2 = (const __half2*)e;
    const float4* p4 = (const float4*)(prev + base);
    float4* spw4 = (float4*)spw;

    float lsum = 0.f;
    #pragma unroll
    for (int k = 0; k < 4; k++) {
        int i = k * 1024 + tid;              // float4 index
        float4 p = p4[i];
        float2 ea = __half22float2(e2[2 * i]);
        float2 eb = __half22float2(e2[2 * i + 1]);

        float4 g;
        g.x = fmaf(a, ea.x, om * p.x);
        g.y = fmaf(a, ea.y, om * p.y);
        g.z = fmaf(a, eb.x, om * p.z);
        g.w = fmaf(a, eb.y, om * p.w);

        int n = i * 4;
        float left = __shfl_up_sync(0xffffffffu, g.w, 1);
        float right = __shfl_down_sync(0xffffffffu, g.x, 1);
        if (lane == 0) {
            int nl = (n + N_ - 1) & (N_ - 1);
            left = fmaf(a, __half2float(e[nl]), om * prev[base + nl]);
        }
        if (lane == 31) {
            int nr = (n + 4) & (N_ - 1);
            right = fmaf(a, __half2float(e[nr]), om * prev[base + nr]);
        }

        float v0 = fmaf(sh0, left, fmaf(sh1, g.x, sh2 * g.y));
        float v1 = fmaf(sh0, g.x, fmaf(sh1, g.y, sh2 * g.z));
        float v2 = fmaf(sh0, g.y, fmaf(sh1, g.z, sh2 * g.w));
        float v3 = fmaf(sh0, g.z, fmaf(sh1, g.w, sh2 * right));

        float w0 = __powf(v0, gamma), w1 = __powf(v1, gamma);
        float w2 = __powf(v2, gamma), w3 = __powf(v3, gamma);
        spw4[i] = make_float4(w0, w1, w2, w3);
        lsum += (w0 + w1) + (w2 + w3);
    }

    #pragma unroll
    for (int o = 16; o; o >>= 1) lsum += __shfl_xor_sync(0xffffffffu, lsum, o);
    if (lane == 0) sr[tid >> 5] = lsum;
    __syncthreads();
    if (tid < 32) {
        float t = sr[tid];
        #pragma unroll
        for (int o = 16; o; o >>= 1) t += __shfl_xor_sync(0xffffffffu, t, o);
        if (tid == 0) sr[32] = t;
    }
    __syncthreads();
    float invT = 1.f / (sr[32] + 1e-6f);

    float4* o4 = (float4*)(out + base);
    #pragma unroll
    for (int k = 0; k < 4; k++) {
        int i = k * 1024 + tid;
        float4 v = spw4[i];
        v.x *= invT; v.y *= invT; v.z *= invT; v.w *= invT;
        o4[i] = v;
    }
}

// ---------------------------------------------------------------------------
extern "C" void kernel_launch(void* const* d_in, const int* in_sizes, int n_in,
                              void* d_out, int out_size) {
    const float* cs   = (const float*)d_in[0];
    const float* prev = (const float*)d_in[1];
    const float* mem  = (const float*)d_in[2];
    const float* Wr   = (const float*)d_in[3];
    const float* br   = (const float*)d_in[4];
    float* out = (float*)d_out;

    static int inited = 0;
    if (!inited) {
        cudaFuncSetAttribute(kfinish, cudaFuncAttributeMaxDynamicSharedMemorySize,
                             N_ * 4);
        inited = 1;
    }

    kparams<<<B_ * H_, 256>>>(cs, Wr, br);
    kdots<<<dim3(N_ / ROWS_PB, B_), 256>>>(mem);
    kfinish<<<B_ * H_, 1024, N_ * 4>>>(prev, out);
}